// round 11
// baseline (speedup 1.0000x reference)
#include <cuda_runtime.h>
#include <cuda_bf16.h>

// ============================================================================
// ECE over N=2^24 samples, 15 bins — register-only hot loop with packed
// f32x2 accumulation.
//
// Identity:  x = c*nb,  d = c - a
//   U_k = sum_i d_i * [x_i > k],  k = 0..14
//   S_b = U_b - U_{b+1} (U_15 = 0);   ece = sum_{b<nb} |S_b| / n
// Self-gating: c<=0 / NaN fail every compare (set.gt ordered -> 0.0f).
//
// R11 vs R10 (32.6us, issue 59%, fma 24 + alu 41.5, latency-bound):
//  * set.gt.f32.f32 (1.0f/0.0f, lat-4 alu) replaces setp+@p add (13-cyc
//    pred-as-guard latency).
//  * ELEMENT-PAIR processing: 15 accumulators are f32x2; one fma.rn.f32x2
//    per bin per TWO elements (FFMA2 is PTX-only on sm_103a). ~24 instr/elem
//    vs 32, fma-class work nearly halved.
//  * d2 = fma.rn.f32x2(a2, (-1,-1), c2) — packed c/a pairs come free from
//    adjacent float4 components.
//  * grid 592 = 4 CTAs/SM exact single wave; launch_bounds(256,4) = 64 regs.
// ============================================================================

#define TPB 256
#define NBINS 15
#define BSTRIDE 16
#define NBLOCKS 592          // 4 CTAs/SM * 148 SMs, exact single wave
#define MAX_BLOCKS 4096

__device__ float g_partial[MAX_BLOCKS * BSTRIDE];
__device__ unsigned int g_count = 0;

#define NEGONE2 0xBF800000BF800000ULL

// Two elements (c1,a1), (c2,a2): for each k, A[k].{lo,hi} += d{1,2}*[x{1,2}>k]
__device__ __forceinline__ void accum15x2(float c1, float a1, float c2, float a2,
                                          float fnb, unsigned long long neg2,
                                          unsigned long long* A) {
    asm("{\n\t"
        ".reg .f32 x1, x2, s1, s2;\n\t"
        ".reg .b64 cp, ap, d2, sp;\n\t"
        "mul.f32 x1, %15, %19;\n\t"
        "mul.f32 x2, %17, %19;\n\t"
        "mov.b64 cp, {%15, %17};\n\t"
        "mov.b64 ap, {%16, %18};\n\t"
        "fma.rn.f32x2 d2, ap, %20, cp;\n\t"            // (c1-a1, c2-a2)
        "set.gt.f32.f32 s1, x1, 0f00000000;\n\t"
        "set.gt.f32.f32 s2, x2, 0f00000000;\n\t"
        "mov.b64 sp, {s1, s2};\n\t"
        "fma.rn.f32x2 %0, sp, d2, %0;\n\t"
        "set.gt.f32.f32 s1, x1, 0f3F800000;\n\t"
        "set.gt.f32.f32 s2, x2, 0f3F800000;\n\t"
        "mov.b64 sp, {s1, s2};\n\t"
        "fma.rn.f32x2 %1, sp, d2, %1;\n\t"
        "set.gt.f32.f32 s1, x1, 0f40000000;\n\t"
        "set.gt.f32.f32 s2, x2, 0f40000000;\n\t"
        "mov.b64 sp, {s1, s2};\n\t"
        "fma.rn.f32x2 %2, sp, d2, %2;\n\t"
        "set.gt.f32.f32 s1, x1, 0f40400000;\n\t"
        "set.gt.f32.f32 s2, x2, 0f40400000;\n\t"
        "mov.b64 sp, {s1, s2};\n\t"
        "fma.rn.f32x2 %3, sp, d2, %3;\n\t"
        "set.gt.f32.f32 s1, x1, 0f40800000;\n\t"
        "set.gt.f32.f32 s2, x2, 0f40800000;\n\t"
        "mov.b64 sp, {s1, s2};\n\t"
        "fma.rn.f32x2 %4, sp, d2, %4;\n\t"
        "set.gt.f32.f32 s1, x1, 0f40A00000;\n\t"
        "set.gt.f32.f32 s2, x2, 0f40A00000;\n\t"
        "mov.b64 sp, {s1, s2};\n\t"
        "fma.rn.f32x2 %5, sp, d2, %5;\n\t"
        "set.gt.f32.f32 s1, x1, 0f40C00000;\n\t"
        "set.gt.f32.f32 s2, x2, 0f40C00000;\n\t"
        "mov.b64 sp, {s1, s2};\n\t"
        "fma.rn.f32x2 %6, sp, d2, %6;\n\t"
        "set.gt.f32.f32 s1, x1, 0f40E00000;\n\t"
        "set.gt.f32.f32 s2, x2, 0f40E00000;\n\t"
        "mov.b64 sp, {s1, s2};\n\t"
        "fma.rn.f32x2 %7, sp, d2, %7;\n\t"
        "set.gt.f32.f32 s1, x1, 0f41000000;\n\t"
        "set.gt.f32.f32 s2, x2, 0f41000000;\n\t"
        "mov.b64 sp, {s1, s2};\n\t"
        "fma.rn.f32x2 %8, sp, d2, %8;\n\t"
        "set.gt.f32.f32 s1, x1, 0f41100000;\n\t"
        "set.gt.f32.f32 s2, x2, 0f41100000;\n\t"
        "mov.b64 sp, {s1, s2};\n\t"
        "fma.rn.f32x2 %9, sp, d2, %9;\n\t"
        "set.gt.f32.f32 s1, x1, 0f41200000;\n\t"
        "set.gt.f32.f32 s2, x2, 0f41200000;\n\t"
        "mov.b64 sp, {s1, s2};\n\t"
        "fma.rn.f32x2 %10, sp, d2, %10;\n\t"
        "set.gt.f32.f32 s1, x1, 0f41300000;\n\t"
        "set.gt.f32.f32 s2, x2, 0f41300000;\n\t"
        "mov.b64 sp, {s1, s2};\n\t"
        "fma.rn.f32x2 %11, sp, d2, %11;\n\t"
        "set.gt.f32.f32 s1, x1, 0f41400000;\n\t"
        "set.gt.f32.f32 s2, x2, 0f41400000;\n\t"
        "mov.b64 sp, {s1, s2};\n\t"
        "fma.rn.f32x2 %12, sp, d2, %12;\n\t"
        "set.gt.f32.f32 s1, x1, 0f41500000;\n\t"
        "set.gt.f32.f32 s2, x2, 0f41500000;\n\t"
        "mov.b64 sp, {s1, s2};\n\t"
        "fma.rn.f32x2 %13, sp, d2, %13;\n\t"
        "set.gt.f32.f32 s1, x1, 0f41600000;\n\t"
        "set.gt.f32.f32 s2, x2, 0f41600000;\n\t"
        "mov.b64 sp, {s1, s2};\n\t"
        "fma.rn.f32x2 %14, sp, d2, %14;\n\t"
        "}"
        : "+l"(A[0]), "+l"(A[1]), "+l"(A[2]), "+l"(A[3]), "+l"(A[4]),
          "+l"(A[5]), "+l"(A[6]), "+l"(A[7]), "+l"(A[8]), "+l"(A[9]),
          "+l"(A[10]), "+l"(A[11]), "+l"(A[12]), "+l"(A[13]), "+l"(A[14])
        : "f"(c1), "f"(a1), "f"(c2), "f"(a2), "f"(fnb), "l"(neg2));
}

__global__ __launch_bounds__(TPB, 4)   // 64 regs: 30 acc + 16 buf + temps
void ece_kernel(const float* __restrict__ conf,
                const float* __restrict__ ac,
                const int* __restrict__ num_bins_p,
                int n,
                float* __restrict__ out) {
    const int tid = threadIdx.x;
    const int nb = *num_bins_p;          // valid for nb <= 15
    const float fnb = (float)nb;
    const unsigned long long neg2 = NEGONE2;

    unsigned long long A[NBINS];
    #pragma unroll
    for (int k = 0; k < NBINS; k++) A[k] = 0ULL;

    const int nvec = n >> 2;
    const float4* __restrict__ c4 = (const float4*)conf;
    const float4* __restrict__ a4 = (const float4*)ac;
    const int S = gridDim.x * blockDim.x;

    int i = blockIdx.x * blockDim.x + tid;
    // 2x unrolled grid-stride: 4 front-batched LDG.128; ~200-instr body
    // hides load latency across 8 warps/SMSP.
    for (; i + S < nvec; i += 2 * S) {
        const float4 c0 = __ldcs(&c4[i]);
        const float4 c1 = __ldcs(&c4[i + S]);
        const float4 a0 = __ldcs(&a4[i]);
        const float4 a1 = __ldcs(&a4[i + S]);
        accum15x2(c0.x, a0.x, c0.y, a0.y, fnb, neg2, A);
        accum15x2(c0.z, a0.z, c0.w, a0.w, fnb, neg2, A);
        accum15x2(c1.x, a1.x, c1.y, a1.y, fnb, neg2, A);
        accum15x2(c1.z, a1.z, c1.w, a1.w, fnb, neg2, A);
    }
    for (; i < nvec; i += S) {
        const float4 c = __ldcs(&c4[i]);
        const float4 a = __ldcs(&a4[i]);
        accum15x2(c.x, a.x, c.y, a.y, fnb, neg2, A);
        accum15x2(c.z, a.z, c.w, a.w, fnb, neg2, A);
    }
    // scalar remainder (n not multiple of 4): block 0 only; hi lane zeroed
    if (blockIdx.x == 0) {
        for (int j = (nvec << 2) + tid; j < n; j += blockDim.x)
            accum15x2(conf[j], ac[j], 0.0f, 0.0f, fnb, neg2, A);
    }

    // ---- block reduction of the 15 per-thread U_k (one-shot) ----
    __shared__ float red[NBINS * TPB];   // 15 KB
    #pragma unroll
    for (int k = 0; k < NBINS; k++) {
        float2 p = *reinterpret_cast<float2*>(&A[k]);
        red[k * TPB + tid] = p.x + p.y;
    }
    __syncthreads();

    for (int s = TPB / 2; s > 0; s >>= 1) {
        if (tid < s) {
            #pragma unroll
            for (int k = 0; k < NBINS; k++)
                red[k * TPB + tid] += red[k * TPB + tid + s];
        }
        __syncthreads();
    }

    if (tid < BSTRIDE)
        g_partial[blockIdx.x * BSTRIDE + tid] =
            (tid < NBINS) ? red[tid * TPB] : 0.0f;   // slot 15 = U_15 = 0

    // ---- last-block tail reduction (no second launch) ----
    __shared__ bool is_last;
    __threadfence();
    if (tid == 0) {
        unsigned int ticket = atomicAdd(&g_count, 1u);
        is_last = (ticket == gridDim.x - 1);
    }
    __syncthreads();

    if (is_last) {
        __threadfence();
        const int total = gridDim.x * BSTRIDE;
        float s = 0.0f;
        for (int e = tid; e < total; e += TPB)
            s += g_partial[e];

        __shared__ float r2[TPB];
        r2[tid] = s;
        __syncthreads();

        __shared__ float U[BSTRIDE];
        if (tid < BSTRIDE) {
            float t = 0.0f;
            #pragma unroll
            for (int k = 0; k < TPB / BSTRIDE; k++)
                t += r2[tid + k * BSTRIDE];
            U[tid] = t;                       // U[15] = 0 automatically
        }
        __syncthreads();

        if (tid == 0) {
            float tot = 0.0f;
            for (int b = 0; b < nb; b++)      // S_b = U_b - U_{b+1}
                tot += fabsf(U[b] - U[b + 1]);
            out[0] = tot / (float)n;
            g_count = 0;                      // reset for next graph replay
        }
    }
}

extern "C" void kernel_launch(void* const* d_in, const int* in_sizes, int n_in,
                              void* d_out, int out_size) {
    const float* conf = (const float*)d_in[0];
    const float* acc  = (const float*)d_in[1];
    const int*   nbp  = (const int*)d_in[2];
    float* out = (float*)d_out;
    const int n = in_sizes[0];

    int nvec = n >> 2;
    int blocks = (nvec + TPB - 1) / TPB;
    if (blocks > NBLOCKS) blocks = NBLOCKS;
    if (blocks < 1) blocks = 1;

    ece_kernel<<<blocks, TPB>>>(conf, acc, nbp, n, out);
}